// round 12
// baseline (speedup 1.0000x reference)
#include <cuda_runtime.h>
#include <cuda_fp16.h>
#include <cstdint>
#include <math.h>

// ---------------------------------------------------------------------------
// Seq2Seq LSTM via mma.sync (HMMA fp16): B=256, T_in=512, F=64, H=512, T_out=64
// Round 12: TWO independent CTAs per SM to decorrelate pipeline stalls.
// 256 CTAs (4M x 64N, 64x32 tiles), 256 threads (8 warps, 16x16 tiles),
// launch_bounds(256,2). 8-stage ring (12KB stages), PAIR groups, walking
// issue pointers. Single-pass fp16, wavefront fusion, fused projection.
// ---------------------------------------------------------------------------

using f16 = __half;

#define Bsz   256
#define Hd    512
#define Fin   64
#define T_IN  512
#define T_OUT 64
#define N4    2048
#define BH    (Bsz*Hd)
#define NBLK  256
#define THR   256

// per-stage smem: A 8K | B 4K
#define OFF_B  8192
#define BUFB   12288
#define NSTAGE 8
#define DSMEM  (NSTAGE*BUFB + 1024)

// ------------------------- device scratch (static) -------------------------
__device__ __align__(16) f16 g_xc[(size_t)T_IN * Bsz * Fin];
__device__ __align__(16) f16 g_hs[(size_t)T_IN * BH];
__device__ __align__(16) f16 g_h1[2][BH];
__device__ __align__(16) f16 g_d0[2][BH];
__device__ __align__(16) f16 g_d1[2][BH];
__device__ float g_pacc[2][Bsz];          // proj ping-pong accumulators

// weights, remapped rows (see remap_row), layout [2048][K] fp16
__device__ __align__(16) f16 gB_x0[N4 * Fin];
__device__ __align__(16) f16 gB_h0[N4 * Hd];
__device__ __align__(16) f16 gB_x1[N4 * Hd];
__device__ __align__(16) f16 gB_h1[N4 * Hd];
__device__ __align__(16) f16 gB_d0[N4 * Hd];
__device__ __align__(16) f16 gB_x1d[N4 * Hd];
__device__ __align__(16) f16 gB_d1[N4 * Hd];

__device__ __align__(16) float g_b0[N4], g_b1[N4], g_bd0[N4], g_bd1[N4], g_Wv[N4];

__device__ unsigned g_cnt;
__device__ volatile unsigned g_gen;

// ------------------------------- asm helpers -------------------------------
#define LDSM4(R, A) \
    asm volatile("ldmatrix.sync.aligned.m8n8.x4.shared.b16 {%0,%1,%2,%3}, [%4];" \
        : "=r"((R)[0]), "=r"((R)[1]), "=r"((R)[2]), "=r"((R)[3]) : "r"(A))

#define MMA(D, A, B) \
    asm volatile("mma.sync.aligned.m16n8k16.row.col.f32.f16.f16.f32 " \
        "{%0,%1,%2,%3}, {%4,%5,%6,%7}, {%8,%9}, {%0,%1,%2,%3};" \
        : "+f"((D)[0]), "+f"((D)[1]), "+f"((D)[2]), "+f"((D)[3]) \
        : "r"((A)[0]), "r"((A)[1]), "r"((A)[2]), "r"((A)[3]), \
          "r"((B)[0]), "r"((B)[1]))

#define CP16(sa, ga) \
    asm volatile("cp.async.cg.shared.global [%0], [%1], 16;" :: "r"(sa), "l"(ga))
#define CP_COMMIT() asm volatile("cp.async.commit_group;")
#define CP_WAIT0()  asm volatile("cp.async.wait_group 0;" ::: "memory")
#define CP_WAIT1()  asm volatile("cp.async.wait_group 1;" ::: "memory")
#define CP_WAIT2()  asm volatile("cp.async.wait_group 2;" ::: "memory")

__device__ __forceinline__ uint32_t smem_u32(const void* p) {
    uint32_t a;
    asm("{ .reg .u64 t; cvta.to.shared.u64 t, %1; cvt.u32.u64 %0, t; }"
        : "=r"(a) : "l"(p));
    return a;
}
__device__ __forceinline__ float sigf(float x) { return 1.0f / (1.0f + expf(-x)); }

__device__ __forceinline__ void grid_sync() {
    __syncthreads();
    if (threadIdx.x == 0) {
        __threadfence();
        unsigned g = g_gen;
        unsigned old = atomicAdd(&g_cnt, 1u);
        if (old == NBLK - 1) {
            g_cnt = 0;
            __threadfence();
            g_gen = g + 1;
        } else {
            while (g_gen == g) __nanosleep(64);
            __threadfence();
        }
    }
    __syncthreads();
}

// ----------------------------- GEMM machinery ------------------------------
struct Seg {
    const f16 *A;   // A [row][K]
    const f16 *B;   // B' [2048][K]
    int K;          // 64 or 512
};

// Warp tile 16x16, single pass fp16; all LDSM offsets precomputed.
__device__ __forceinline__ void compute_chunk(uint32_t sbase, float acc[2][4],
                                              const uint32_t* asw,
                                              const uint32_t* bsw) {
#pragma unroll
    for (int ka = 0; ka < 4; ++ka) {
        uint32_t a[4], b[4];
        LDSM4(a, sbase + asw[ka]);
        LDSM4(b, sbase + bsw[ka]);
        MMA(acc[0], a, b);
        MMA(acc[1], a, b + 2);
    }
}

// 8-stage ring (4 pairs), PAIR groups, lookahead 3 pairs. Issue of pair p+3
// lands in the slots of pair p-1, already consumed before this iter's sync.
__device__ __forceinline__ void pipe_gemm(uint32_t dsm32, const Seg* segs, int nseg,
                                          int split, float aA[2][4], float aB[2][4],
                                          int bm, int colb, int tid,
                                          const uint32_t* asw, const uint32_t* bsw) {
    int tot = 0;
#pragma unroll
    for (int i = 0; i < 4; ++i) if (i < nseg) tot += segs[i].K >> 6;
    const int npairs = (tot + 1) >> 1;

    const int rowa = tid >> 3, sg8 = (tid & 7) * 8;
    const uint32_t swA0 = (uint32_t)((tid * 16) ^ (((tid * 16) >> 3) & 0x70));
    const int t2 = (tid + 256) * 16;
    const uint32_t swA1 = (uint32_t)(t2 ^ ((t2 >> 3) & 0x70));
    const uint32_t swB  = OFF_B + swA0;
    const int ra512_0 = (bm + rowa) * 512 + sg8;
    const int ra512_1 = ra512_0 + 32 * 512;
    const int rb512   = (colb + rowa) * 512 + sg8;

    // walking issue pointers; reseed at (rare) segment boundaries
    const f16 *pA0, *pA1, *pB;
    if (segs[0].K == 64) {
        pA0 = segs[0].A + (bm + rowa) * 64 + sg8;
        pA1 = pA0 + 32 * 64;
        pB  = segs[0].B + (colb + rowa) * 64 + sg8;
    } else {
        pA0 = segs[0].A + ra512_0;
        pA1 = segs[0].A + ra512_1;
        pB  = segs[0].B + rb512;
    }
    int rem = segs[0].K >> 6;
    int si = 0;
    int issued = 0;
    uint32_t ibase = dsm32;
    const uint32_t wrap = dsm32 + NSTAGE * BUFB;

    auto issue1 = [&]() {
        CP16(ibase + swA0, pA0);
        CP16(ibase + swA1, pA1);
        CP16(ibase + swB,  pB);
        ibase += BUFB;
        if (ibase == wrap) ibase = dsm32;
        ++issued;
        if (--rem == 0) {
            ++si;
            if (si == 1 && nseg > 1) {
                pA0 = segs[1].A + ra512_0; pA1 = segs[1].A + ra512_1;
                pB = segs[1].B + rb512; rem = segs[1].K >> 6;
            } else if (si == 2 && nseg > 2) {
                pA0 = segs[2].A + ra512_0; pA1 = segs[2].A + ra512_1;
                pB = segs[2].B + rb512; rem = segs[2].K >> 6;
            } else if (si == 3 && nseg > 3) {
                pA0 = segs[3].A + ra512_0; pA1 = segs[3].A + ra512_1;
                pB = segs[3].B + rb512; rem = segs[3].K >> 6;
            }
        } else {
            pA0 += 64; pA1 += 64; pB += 64;
        }
    };

    // prefill up to 3 pairs
    {
        const int pre = npairs < 3 ? npairs : 3;
        for (int g = 0; g < pre; ++g) {
            issue1();
            if (issued < tot) issue1();
            CP_COMMIT();
        }
    }

    uint32_t cbase = dsm32;
    int c = 0;
    for (int p = 0; p < npairs; ++p) {
        const int ahead = npairs - 1 - p;
        if (ahead >= 2)      CP_WAIT2();
        else if (ahead == 1) CP_WAIT1();
        else                 CP_WAIT0();
        __syncthreads();
        if (p + 3 < npairs) {
            issue1();
            if (issued < tot) issue1();
            CP_COMMIT();
        }
#pragma unroll
        for (int j = 0; j < 2; ++j) {
            if (c < tot) {
                compute_chunk(cbase, c < split ? aA : aB, asw, bsw);
                cbase += BUFB;
                if (cbase == wrap) cbase = dsm32;
                ++c;
            }
        }
    }
}

#define ZERO_ACC(A) \
    do { _Pragma("unroll") for (int _a = 0; _a < 2; ++_a) \
         _Pragma("unroll") for (int _d = 0; _d < 4; ++_d) (A)[_a][_d] = 0.0f; } while (0)

// Epilogue: thread owns rows {m, m+8} x ONE unit (all 4 gates).
// acc[0][rr*2+p]: p=0 -> i, p=1 -> f; acc[1][..]: p=0 -> g, p=1 -> o.
__device__ __forceinline__ void epilogue_lstm(float acc[2][4], float* c,
                                              const float* bias,
                                              const float* prevv, const float* Wv,
                                              f16* H,
                                              const float* pjW, float* pacc,
                                              int bm, int G16, int wm, int lane) {
    const int q = lane & 3, r = lane >> 2;
    const float2* b2 = (const float2*)bias;
    const float2 bIF = b2[G16 * 8 + q];
    const float2 bGO = b2[G16 * 8 + 4 + q];
    float2 wIF = make_float2(0.f, 0.f), wGO = make_float2(0.f, 0.f);
    if (Wv) {
        const float2* w2 = (const float2*)Wv;
        wIF = w2[G16 * 8 + q];
        wGO = w2[G16 * 8 + 4 + q];
    }
    const int u = G16 * 4 + q;      // original hidden-unit index
    float pw = 0.0f;
    if (pjW) pw = pjW[u];
    float rsum[2] = {0.0f, 0.0f};
#pragma unroll
    for (int rr = 0; rr < 2; ++rr) {
        const int m = bm + wm * 16 + r + rr * 8;
        float gi = acc[0][rr * 2 + 0] + bIF.x;
        float gf = acc[0][rr * 2 + 1] + bIF.y;
        float gg = acc[1][rr * 2 + 0] + bGO.x;
        float go = acc[1][rr * 2 + 1] + bGO.y;
        if (prevv) {
            const float pv = prevv[m];
            gi = fmaf(pv, wIF.x, gi); gf = fmaf(pv, wIF.y, gf);
            gg = fmaf(pv, wGO.x, gg); go = fmaf(pv, wGO.y, go);
        }
        float cn = sigf(gf) * c[rr] + sigf(gi) * tanhf(gg);
        float hn = sigf(go) * tanhf(cn);
        c[rr] = cn;
        if (pjW) rsum[rr] = hn * pw;
        H[(size_t)m * Hd + u] = __float2half(hn);
    }
    if (pjW) {
#pragma unroll
        for (int rr = 0; rr < 2; ++rr) {
            rsum[rr] += __shfl_xor_sync(0xffffffffu, rsum[rr], 1);
            rsum[rr] += __shfl_xor_sync(0xffffffffu, rsum[rr], 2);
        }
        if (q == 0) {
            atomicAdd(&pacc[bm + wm * 16 + r], rsum[0]);
            atomicAdd(&pacc[bm + wm * 16 + r + 8], rsum[1]);
        }
    }
}

// ------------------------------- prep kernel -------------------------------
// gate g (0..3), unit j (0..511) -> col = 16*(j>>2) + 2*(j&3) + (g&1) + 8*(g>>1)
__device__ __forceinline__ int remap_row(int r) {
    const int g = r >> 9, j = r & 511;
    return ((j >> 2) << 4) + ((j & 3) << 1) + (g & 1) + ((g >> 1) << 3);
}

__global__ void prep_kernel(
    const float* __restrict__ x,
    const float* __restrict__ e0Wih, const float* __restrict__ e0Whh,
    const float* __restrict__ e0bih, const float* __restrict__ e0bhh,
    const float* __restrict__ e1Wih, const float* __restrict__ e1Whh,
    const float* __restrict__ e1bih, const float* __restrict__ e1bhh,
    const float* __restrict__ d0Wih, const float* __restrict__ d0Whh,
    const float* __restrict__ d0bih, const float* __restrict__ d0bhh,
    const float* __restrict__ d1Wih, const float* __restrict__ d1Whh,
    const float* __restrict__ d1bih, const float* __restrict__ d1bhh,
    const float* __restrict__ projb) {
    const size_t FULL = (size_t)N4 * Hd;
    long long idx = (long long)blockIdx.x * 256 + threadIdx.x;

    if (idx < (long long)(6 * FULL)) {
        int seg = (int)(idx / FULL);
        size_t i = (size_t)(idx % FULL);
        int r = (int)(i / Hd), k = (int)(i % Hd);
        size_t dst = (size_t)remap_row(r) * Hd + k;
        const float* src; f16* d;
        switch (seg) {
            case 0: src = e0Whh; d = gB_h0;  break;
            case 1: src = e1Wih; d = gB_x1;  break;
            case 2: src = e1Whh; d = gB_h1;  break;
            case 3: src = d0Whh; d = gB_d0;  break;
            case 4: src = d1Wih; d = gB_x1d; break;
            default: src = d1Whh; d = gB_d1; break;
        }
        d[dst] = __float2half(src[i]);
        return;
    }
    idx -= 6LL * FULL;

    if (idx < (long long)N4 * Fin) {   // Wx0
        size_t i = (size_t)idx;
        int r = (int)(i / Fin), k = (int)(i % Fin);
        gB_x0[(size_t)remap_row(r) * Fin + k] = __float2half(e0Wih[i]);
        return;
    }
    idx -= (long long)N4 * Fin;

    if (idx < (long long)Bsz * T_IN * Fin) {   // x -> [t][b][f]
        size_t i = (size_t)idx;
        int b = (int)(i / (T_IN * Fin));
        int t = (int)((i / Fin) % T_IN);
        int f = (int)(i % Fin);
        g_xc[(size_t)t * Bsz * Fin + b * Fin + f] = __float2half(x[i]);
        return;
    }
    idx -= (long long)Bsz * T_IN * Fin;

    if (idx < N4) {                    // biases + Wv, remapped (fp32)
        int r = (int)idx;
        int dst = remap_row(r);
        g_Wv[dst]  = d0Wih[r];
        g_b0[dst]  = e0bih[r] + e0bhh[r];
        g_b1[dst]  = e1bih[r] + e1bhh[r];
        g_bd0[dst] = d0bih[r] + d0bhh[r];
        g_bd1[dst] = d1bih[r] + d1bhh[r];
        return;
    }
    idx -= N4;

    if (idx < Bsz) {                   // prev slot0 = x[:, -1, -1]; slot1 = projb
        g_pacc[0][idx] = x[(size_t)(idx + 1) * T_IN * Fin - 1];
        g_pacc[1][idx] = projb[0];
        return;
    }
    idx -= Bsz;
    if (idx == 0) g_cnt = 0;
}

// ------------------------------ main kernel --------------------------------
__global__ void __launch_bounds__(THR, 2)
main_kernel(const float* __restrict__ projW,
            const float* __restrict__ projb,
            float* __restrict__ out) {
    extern __shared__ char dsm_raw[];
    const uint32_t raw32 = smem_u32(dsm_raw);
    const uint32_t dsm32 = (raw32 + 1023u) & ~1023u;

    const int tid  = threadIdx.x;
    const int lane = tid & 31;
    const int w    = tid >> 5;         // 0..7
    const int wm   = w & 3;            // M slice (16 rows)
    const int wn   = w >> 2;           // N slice (16 cols)
    const int bid  = blockIdx.x;       // 256 CTAs: 4M x 64N
    const int mT   = bid >> 6;
    const int nT   = bid & 63;
    const int bm   = mT * 64;
    const int colb = nT * 32;
    const int G16  = nT * 2 + wn;      // 16-col block = 4 units x 4 gates

    // Precompute swizzled LDSM offsets (stage-relative); hot loop is IADD-only.
    uint32_t asw[4], bsw[4];
    {
        const int abase = (wm * 16 + (lane & 15)) * 128 + ((lane >> 4) << 4);
        const int bbase = (wn * 16 + (lane & 7) + ((lane >> 4) << 3)) * 128
                        + (((lane >> 3) & 1) << 4);
#pragma unroll
        for (int ka = 0; ka < 4; ++ka) {
            const int ao = abase + ka * 32;
            asw[ka] = ao ^ ((ao >> 3) & 0x70);
            const int bo = bbase + ka * 32;
            bsw[ka] = OFF_B + (bo ^ ((bo >> 3) & 0x70));
        }
    }

    float accA[2][4], accB[2][4];
    float c0[2], c1[2];
    c0[0] = c0[1] = c1[0] = c1[1] = 0.0f;

    Seg segs[4];

    // -------- fused encoder wavefront: superstep s = enc0(s) + enc1(s-1) ----
    for (int s = 0; s <= T_IN; ++s) {
        int ns = 0, split = 0;
        if (s < T_IN) {
            segs[ns++] = { g_xc + (size_t)s * Bsz * Fin, gB_x0, Fin };
            if (s) segs[ns++] = { g_hs + (size_t)(s - 1) * BH, gB_h0, Hd };
            split = s ? 9 : 1;
        }
        if (s >= 1) {
            segs[ns++] = { g_hs + (size_t)(s - 1) * BH, gB_x1, Hd };
            if (s >= 2) segs[ns++] = { &g_h1[s & 1][0], gB_h1, Hd };
        }
        ZERO_ACC(accA); ZERO_ACC(accB);
        pipe_gemm(dsm32, segs, ns, split, accA, accB, bm, colb, tid, asw, bsw);
        if (s < T_IN)
            epilogue_lstm(accA, c0, g_b0, nullptr, nullptr,
                          g_hs + (size_t)s * BH, nullptr, nullptr, bm, G16, wm, lane);
        if (s >= 1)
            epilogue_lstm(accB, c1, g_b1, nullptr, nullptr,
                          &g_h1[(s - 1) & 1][0], nullptr, nullptr, bm, G16, wm, lane);
        grid_sync();
    }

    // -------------------------------- decoder -------------------------------
    const f16 *h0p = g_hs + (size_t)(T_IN - 1) * BH;
    const f16 *h1p = &g_h1[(T_IN - 1) & 1][0];
    const float pjb = projb[0];

    for (int t = 0; t < T_OUT; ++t) {
        // phase A: dec0(t); side tasks: emit out[:,t-1], reseed next slot
        if (bid == 0 && t >= 1)
            out[(size_t)tid * T_OUT + (t - 1)] = g_pacc[t & 1][tid];
        if (bid == 1)
            g_pacc[(t + 1) & 1][tid] = pjb;

        segs[0] = { h0p, gB_d0, Hd };
        ZERO_ACC(accA);
        pipe_gemm(dsm32, segs, 1, 8, accA, accA, bm, colb, tid, asw, bsw);
        epilogue_lstm(accA, c0, g_bd0, &g_pacc[t & 1][0], g_Wv,
                      &g_d0[t & 1][0], nullptr, nullptr, bm, G16, wm, lane);
        grid_sync();

        // phase B: dec1(t) + fused projection into pacc[(t+1)&1]
        segs[0] = { &g_d0[t & 1][0], gB_x1d, Hd };
        segs[1] = { h1p, gB_d1, Hd };
        ZERO_ACC(accA);
        pipe_gemm(dsm32, segs, 2, 16, accA, accA, bm, colb, tid, asw, bsw);
        epilogue_lstm(accA, c1, g_bd1, nullptr, nullptr,
                      &g_d1[t & 1][0], projW, &g_pacc[(t + 1) & 1][0],
                      bm, G16, wm, lane);
        grid_sync();

        h0p = &g_d0[t & 1][0];
        h1p = &g_d1[t & 1][0];
    }

    // final output column (t = 63): slot (63+1)&1 = 0
    if (bid == 0)
        out[(size_t)tid * T_OUT + (T_OUT - 1)] = g_pacc[0][tid];
}

// ------------------------------- host side ---------------------------------
extern "C" void kernel_launch(void* const* d_in, const int* in_sizes, int n_in,
                              void* d_out, int out_size) {
    const float* x      = (const float*)d_in[0];
    const float* e0Wih  = (const float*)d_in[2];
    const float* e0Whh  = (const float*)d_in[3];
    const float* e0bih  = (const float*)d_in[4];
    const float* e0bhh  = (const float*)d_in[5];
    const float* e1Wih  = (const float*)d_in[6];
    const float* e1Whh  = (const float*)d_in[7];
    const float* e1bih  = (const float*)d_in[8];
    const float* e1bhh  = (const float*)d_in[9];
    const float* d0Wih  = (const float*)d_in[10];
    const float* d0Whh  = (const float*)d_in[11];
    const float* d0bih  = (const float*)d_in[12];
    const float* d0bhh  = (const float*)d_in[13];
    const float* d1Wih  = (const float*)d_in[14];
    const float* d1Whh  = (const float*)d_in[15];
    const float* d1bih  = (const float*)d_in[16];
    const float* d1bhh  = (const float*)d_in[17];
    const float* projW  = (const float*)d_in[18];
    const float* projb  = (const float*)d_in[19];
    float* out = (float*)d_out;

    const long long total = 6LL * N4 * Hd + (long long)N4 * Fin
                          + (long long)Bsz * T_IN * Fin + N4 + Bsz + 1;
    const int nblk = (int)((total + 255) / 256);
    prep_kernel<<<nblk, 256>>>(x,
        e0Wih, e0Whh, e0bih, e0bhh,
        e1Wih, e1Whh, e1bih, e1bhh,
        d0Wih, d0Whh, d0bih, d0bhh,
        d1Wih, d1Whh, d1bih, d1bhh, projb);

    cudaFuncSetAttribute(main_kernel, cudaFuncAttributeMaxDynamicSharedMemorySize, DSMEM);
    main_kernel<<<NBLK, THR, DSMEM>>>(projW, projb, out);
}

// round 13
// speedup vs baseline: 1.1206x; 1.1206x over previous
#include <cuda_runtime.h>
#include <cuda_fp16.h>
#include <cstdint>
#include <math.h>

// ---------------------------------------------------------------------------
// Seq2Seq LSTM via mma.sync (HMMA fp16): B=256, T_in=512, F=64, H=512, T_out=64
// Round 13: revert to round-11 champion shape (128 CTAs, 512 thr, 12-stage
// quad ring) + FAST-MATH epilogue: MUFU-based sigmoid/tanh (__expf) instead of
// accurate expf/tanhf, __ldg for epilogue constants. Epilogues execute at full
// convergence points so their instruction count is fully exposed.
// ---------------------------------------------------------------------------

using f16 = __half;

#define Bsz   256
#define Hd    512
#define Fin   64
#define T_IN  512
#define T_OUT 64
#define N4    2048
#define BH    (Bsz*Hd)
#define NBLK  128
#define THR   512

// per-stage smem: A 8K | B 8K
#define OFF_B  8192
#define BUFB   16384
#define NSTAGE 12
#define DSMEM  (NSTAGE*BUFB + 1024)

// ------------------------- device scratch (static) -------------------------
__device__ __align__(16) f16 g_xc[(size_t)T_IN * Bsz * Fin];
__device__ __align__(16) f16 g_hs[(size_t)T_IN * BH];
__device__ __align__(16) f16 g_h1[2][BH];
__device__ __align__(16) f16 g_d0[2][BH];
__device__ __align__(16) f16 g_d1[2][BH];
__device__ float g_pacc[2][Bsz];          // proj ping-pong accumulators

// weights, remapped rows (see remap_row), layout [2048][K] fp16
__device__ __align__(16) f16 gB_x0[N4 * Fin];
__device__ __align__(16) f16 gB_h0[N4 * Hd];
__device__ __align__(16) f16 gB_x1[N4 * Hd];
__device__ __align__(16) f16 gB_h1[N4 * Hd];
__device__ __align__(16) f16 gB_d0[N4 * Hd];
__device__ __align__(16) f16 gB_x1d[N4 * Hd];
__device__ __align__(16) f16 gB_d1[N4 * Hd];

__device__ __align__(16) float g_b0[N4], g_b1[N4], g_bd0[N4], g_bd1[N4], g_Wv[N4];

__device__ unsigned g_cnt;
__device__ volatile unsigned g_gen;

// ------------------------------- asm helpers -------------------------------
#define LDSM4(R, A) \
    asm volatile("ldmatrix.sync.aligned.m8n8.x4.shared.b16 {%0,%1,%2,%3}, [%4];" \
        : "=r"((R)[0]), "=r"((R)[1]), "=r"((R)[2]), "=r"((R)[3]) : "r"(A))

#define MMA(D, A, B) \
    asm volatile("mma.sync.aligned.m16n8k16.row.col.f32.f16.f16.f32 " \
        "{%0,%1,%2,%3}, {%4,%5,%6,%7}, {%8,%9}, {%0,%1,%2,%3};" \
        : "+f"((D)[0]), "+f"((D)[1]), "+f"((D)[2]), "+f"((D)[3]) \
        : "r"((A)[0]), "r"((A)[1]), "r"((A)[2]), "r"((A)[3]), \
          "r"((B)[0]), "r"((B)[1]))

#define CP16(sa, ga) \
    asm volatile("cp.async.cg.shared.global [%0], [%1], 16;" :: "r"(sa), "l"(ga))
#define CP_COMMIT() asm volatile("cp.async.commit_group;")
#define CP_WAIT0()  asm volatile("cp.async.wait_group 0;" ::: "memory")
#define CP_WAIT1()  asm volatile("cp.async.wait_group 1;" ::: "memory")

__device__ __forceinline__ uint32_t smem_u32(const void* p) {
    uint32_t a;
    asm("{ .reg .u64 t; cvta.to.shared.u64 t, %1; cvt.u32.u64 %0, t; }"
        : "=r"(a) : "l"(p));
    return a;
}

// Fast activations: MUFU-based. |err| ~2^-21, far below fp16 gate noise.
__device__ __forceinline__ float sigf(float x) {
    return __fdividef(1.0f, 1.0f + __expf(-x));
}
__device__ __forceinline__ float tanhf_fast(float x) {
    // tanh(x) = 1 - 2/(exp(2x)+1)
    return 1.0f - __fdividef(2.0f, __expf(2.0f * x) + 1.0f);
}

__device__ __forceinline__ void grid_sync() {
    __syncthreads();
    if (threadIdx.x == 0) {
        __threadfence();
        unsigned g = g_gen;
        unsigned old = atomicAdd(&g_cnt, 1u);
        if (old == NBLK - 1) {
            g_cnt = 0;
            __threadfence();
            g_gen = g + 1;
        } else {
            while (g_gen == g) __nanosleep(64);
            __threadfence();
        }
    }
    __syncthreads();
}

// ----------------------------- GEMM machinery ------------------------------
struct Seg {
    const f16 *A;   // A [row][K]
    const f16 *B;   // B' [2048][K]
    int K;          // 64 or 512
};

// Warp tile 16x16, single pass fp16; all LDSM offsets precomputed.
__device__ __forceinline__ void compute_chunk(uint32_t sbase, float acc[2][4],
                                              const uint32_t* asw,
                                              const uint32_t* bsw) {
#pragma unroll
    for (int ka = 0; ka < 4; ++ka) {
        uint32_t a[4], b[4];
        LDSM4(a, sbase + asw[ka]);
        LDSM4(b, sbase + bsw[ka]);
        MMA(acc[0], a, b);
        MMA(acc[1], a, b + 2);
    }
}

// 12-stage ring, QUAD groups: one wait + one syncthreads per 4 chunks.
__device__ __forceinline__ void pipe_gemm(uint32_t dsm32, const Seg* segs, int nseg,
                                          int split, float aA[2][4], float aB[2][4],
                                          int bm, int colb, int tid,
                                          const uint32_t* asw, const uint32_t* bsw) {
    int tot = 0;
#pragma unroll
    for (int i = 0; i < 4; ++i) if (i < nseg) tot += segs[i].K >> 6;
    const int G = (tot + 3) >> 2;

    const int row = tid >> 3, sg8 = (tid & 7) * 8;
    const uint32_t swA = (uint32_t)((tid * 16) ^ (((tid * 16) >> 3) & 0x70));
    const uint32_t swB = swA + OFF_B;
    const int ra512 = (bm + row) * 512 + sg8;
    const int rb512 = (colb + row) * 512 + sg8;

    // issue cursor: walking pointers, reseed at (rare) segment boundaries
    const f16* pA = segs[0].A + (segs[0].K == 64 ? (bm + row) * 64 + sg8 : ra512);
    const f16* pB = segs[0].B + (segs[0].K == 64 ? (colb + row) * 64 + sg8 : rb512);
    int rem = segs[0].K >> 6;
    int si = 0;
    int issued = 0;
    uint32_t ibase = dsm32;
    const uint32_t wrap = dsm32 + NSTAGE * BUFB;

    auto issue1 = [&]() {
        CP16(ibase + swA, pA);
        CP16(ibase + swB, pB);
        ibase += BUFB;
        if (ibase == wrap) ibase = dsm32;
        ++issued;
        if (--rem == 0) {
            ++si;
            if (si == 1 && nseg > 1) { pA = segs[1].A + ra512; pB = segs[1].B + rb512; rem = segs[1].K >> 6; }
            else if (si == 2 && nseg > 2) { pA = segs[2].A + ra512; pB = segs[2].B + rb512; rem = segs[2].K >> 6; }
            else if (si == 3 && nseg > 3) { pA = segs[3].A + ra512; pB = segs[3].B + rb512; rem = segs[3].K >> 6; }
        } else {
            pA += 64;
            pB += 64;
        }
    };

    // prefill 2 groups
    {
        const int pre = G < 2 ? G : 2;
        for (int g = 0; g < pre; ++g) {
#pragma unroll
            for (int j = 0; j < 4; ++j) if (issued < tot) issue1();
            CP_COMMIT();
        }
    }

    uint32_t cbase = dsm32;
    int c = 0;
    for (int g = 0; g < G; ++g) {
        if (g + 1 < G) CP_WAIT1();
        else           CP_WAIT0();
        __syncthreads();
        if (g + 2 < G) {
#pragma unroll
            for (int j = 0; j < 4; ++j) if (issued < tot) issue1();
            CP_COMMIT();
        }
#pragma unroll
        for (int j = 0; j < 4; ++j) {
            if (c < tot) {
                compute_chunk(cbase, c < split ? aA : aB, asw, bsw);
                cbase += BUFB;
                if (cbase == wrap) cbase = dsm32;
                ++c;
            }
        }
    }
}

#define ZERO_ACC(A) \
    do { _Pragma("unroll") for (int _a = 0; _a < 2; ++_a) \
         _Pragma("unroll") for (int _d = 0; _d < 4; ++_d) (A)[_a][_d] = 0.0f; } while (0)

// Epilogue: thread owns rows {m, m+8} x ONE unit (all 4 gates).
// acc[0][rr*2+p]: p=0 -> i, p=1 -> f; acc[1][..]: p=0 -> g, p=1 -> o.
__device__ __forceinline__ void epilogue_lstm(float acc[2][4], float* c,
                                              const float* bias,
                                              const float* prevv, const float* Wv,
                                              f16* H,
                                              const float* pjW, float* pacc,
                                              int bm, int G16, int wm, int lane) {
    const int q = lane & 3, r = lane >> 2;
    const float2* b2 = (const float2*)bias;
    const float2 bIF = __ldg(&b2[G16 * 8 + q]);
    const float2 bGO = __ldg(&b2[G16 * 8 + 4 + q]);
    float2 wIF = make_float2(0.f, 0.f), wGO = make_float2(0.f, 0.f);
    if (Wv) {
        const float2* w2 = (const float2*)Wv;
        wIF = __ldg(&w2[G16 * 8 + q]);
        wGO = __ldg(&w2[G16 * 8 + 4 + q]);
    }
    const int u = G16 * 4 + q;      // original hidden-unit index
    float pw = 0.0f;
    if (pjW) pw = __ldg(&pjW[u]);
    float rsum[2] = {0.0f, 0.0f};
#pragma unroll
    for (int rr = 0; rr < 2; ++rr) {
        const int m = bm + wm * 16 + r + rr * 8;
        float gi = acc[0][rr * 2 + 0] + bIF.x;
        float gf = acc[0][rr * 2 + 1] + bIF.y;
        float gg = acc[1][rr * 2 + 0] + bGO.x;
        float go = acc[1][rr * 2 + 1] + bGO.y;
        if (prevv) {
            const float pv = prevv[m];
            gi = fmaf(pv, wIF.x, gi); gf = fmaf(pv, wIF.y, gf);
            gg = fmaf(pv, wGO.x, gg); go = fmaf(pv, wGO.y, go);
        }
        float cn = sigf(gf) * c[rr] + sigf(gi) * tanhf_fast(gg);
        float hn = sigf(go) * tanhf_fast(cn);
        c[rr] = cn;
        if (pjW) rsum[rr] = hn * pw;
        H[(size_t)m * Hd + u] = __float2half(hn);
    }
    if (pjW) {
#pragma unroll
        for (int rr = 0; rr < 2; ++rr) {
            rsum[rr] += __shfl_xor_sync(0xffffffffu, rsum[rr], 1);
            rsum[rr] += __shfl_xor_sync(0xffffffffu, rsum[rr], 2);
        }
        if (q == 0) {
            atomicAdd(&pacc[bm + wm * 16 + r], rsum[0]);
            atomicAdd(&pacc[bm + wm * 16 + r + 8], rsum[1]);
        }
    }
}

// ------------------------------- prep kernel -------------------------------
// gate g (0..3), unit j (0..511) -> col = 16*(j>>2) + 2*(j&3) + (g&1) + 8*(g>>1)
__device__ __forceinline__ int remap_row(int r) {
    const int g = r >> 9, j = r & 511;
    return ((j >> 2) << 4) + ((j & 3) << 1) + (g & 1) + ((g >> 1) << 3);
}

__global__ void prep_kernel(
    const float* __restrict__ x,
    const float* __restrict__ e0Wih, const float* __restrict__ e0Whh,
    const float* __restrict__ e0bih, const float* __restrict__ e0bhh,
    const float* __restrict__ e1Wih, const float* __restrict__ e1Whh,
    const float* __restrict__ e1bih, const float* __restrict__ e1bhh,
    const float* __restrict__ d0Wih, const float* __restrict__ d0Whh,
    const float* __restrict__ d0bih, const float* __restrict__ d0bhh,
    const float* __restrict__ d1Wih, const float* __restrict__ d1Whh,
    const float* __restrict__ d1bih, const float* __restrict__ d1bhh,
    const float* __restrict__ projb) {
    const size_t FULL = (size_t)N4 * Hd;
    long long idx = (long long)blockIdx.x * 256 + threadIdx.x;

    if (idx < (long long)(6 * FULL)) {
        int seg = (int)(idx / FULL);
        size_t i = (size_t)(idx % FULL);
        int r = (int)(i / Hd), k = (int)(i % Hd);
        size_t dst = (size_t)remap_row(r) * Hd + k;
        const float* src; f16* d;
        switch (seg) {
            case 0: src = e0Whh; d = gB_h0;  break;
            case 1: src = e1Wih; d = gB_x1;  break;
            case 2: src = e1Whh; d = gB_h1;  break;
            case 3: src = d0Whh; d = gB_d0;  break;
            case 4: src = d1Wih; d = gB_x1d; break;
            default: src = d1Whh; d = gB_d1; break;
        }
        d[dst] = __float2half(src[i]);
        return;
    }
    idx -= 6LL * FULL;

    if (idx < (long long)N4 * Fin) {   // Wx0
        size_t i = (size_t)idx;
        int r = (int)(i / Fin), k = (int)(i % Fin);
        gB_x0[(size_t)remap_row(r) * Fin + k] = __float2half(e0Wih[i]);
        return;
    }
    idx -= (long long)N4 * Fin;

    if (idx < (long long)Bsz * T_IN * Fin) {   // x -> [t][b][f]
        size_t i = (size_t)idx;
        int b = (int)(i / (T_IN * Fin));
        int t = (int)((i / Fin) % T_IN);
        int f = (int)(i % Fin);
        g_xc[(size_t)t * Bsz * Fin + b * Fin + f] = __float2half(x[i]);
        return;
    }
    idx -= (long long)Bsz * T_IN * Fin;

    if (idx < N4) {                    // biases + Wv, remapped (fp32)
        int r = (int)idx;
        int dst = remap_row(r);
        g_Wv[dst]  = d0Wih[r];
        g_b0[dst]  = e0bih[r] + e0bhh[r];
        g_b1[dst]  = e1bih[r] + e1bhh[r];
        g_bd0[dst] = d0bih[r] + d0bhh[r];
        g_bd1[dst] = d1bih[r] + d1bhh[r];
        return;
    }
    idx -= N4;

    if (idx < Bsz) {                   // prev slot0 = x[:, -1, -1]; slot1 = projb
        g_pacc[0][idx] = x[(size_t)(idx + 1) * T_IN * Fin - 1];
        g_pacc[1][idx] = projb[0];
        return;
    }
    idx -= Bsz;
    if (idx == 0) g_cnt = 0;
}

// ------------------------------ main kernel --------------------------------
__global__ void __launch_bounds__(THR, 1)
main_kernel(const float* __restrict__ projW,
            const float* __restrict__ projb,
            float* __restrict__ out) {
    extern __shared__ char dsm_raw[];
    const uint32_t raw32 = smem_u32(dsm_raw);
    const uint32_t dsm32 = (raw32 + 1023u) & ~1023u;

    const int tid  = threadIdx.x;
    const int lane = tid & 31;
    const int w    = tid >> 5;         // 0..15
    const int wm   = w & 3;            // M slice (16 rows)
    const int wn   = w >> 2;           // N slice (16 cols)
    const int bid  = blockIdx.x;       // 128 CTAs: 4M x 32N
    const int mT   = bid >> 5;
    const int nT   = bid & 31;
    const int bm   = mT * 64;
    const int colb = nT * 64;
    const int G16  = nT * 4 + wn;      // 16-col block = 4 units x 4 gates

    // Precompute swizzled LDSM offsets (stage-relative); hot loop is IADD-only.
    uint32_t asw[4], bsw[4];
    {
        const int abase = (wm * 16 + (lane & 15)) * 128 + ((lane >> 4) << 4);
        const int bbase = (wn * 16 + (lane & 7) + ((lane >> 4) << 3)) * 128
                        + (((lane >> 3) & 1) << 4);
#pragma unroll
        for (int ka = 0; ka < 4; ++ka) {
            const int ao = abase + ka * 32;
            asw[ka] = ao ^ ((ao >> 3) & 0x70);
            const int bo = bbase + ka * 32;
            bsw[ka] = OFF_B + (bo ^ ((bo >> 3) & 0x70));
        }
    }

    float accA[2][4], accB[2][4];
    float c0[2], c1[2];
    c0[0] = c0[1] = c1[0] = c1[1] = 0.0f;

    Seg segs[4];

    // -------- fused encoder wavefront: superstep s = enc0(s) + enc1(s-1) ----
    for (int s = 0; s <= T_IN; ++s) {
        int ns = 0, split = 0;
        if (s < T_IN) {
            segs[ns++] = { g_xc + (size_t)s * Bsz * Fin, gB_x0, Fin };
            if (s) segs[ns++] = { g_hs + (size_t)(s - 1) * BH, gB_h0, Hd };
            split = s ? 9 : 1;
        }
        if (s >= 1) {
            segs[ns++] = { g_hs + (size_t)(s - 1) * BH, gB_x1, Hd };
            if (s >= 2) segs[ns++] = { &g_h1[s & 1][0], gB_h1, Hd };
        }
        ZERO_ACC(accA); ZERO_ACC(accB);
        pipe_gemm(dsm32, segs, ns, split, accA, accB, bm, colb, tid, asw, bsw);
        if (s < T_IN)
            epilogue_lstm(accA, c0, g_b0, nullptr, nullptr,
                          g_hs + (size_t)s * BH, nullptr, nullptr, bm, G16, wm, lane);
        if (s >= 1)
            epilogue_lstm(accB, c1, g_b1, nullptr, nullptr,
                          &g_h1[(s - 1) & 1][0], nullptr, nullptr, bm, G16, wm, lane);
        grid_sync();
    }

    // -------------------------------- decoder -------------------------------
    const f16 *h0p = g_hs + (size_t)(T_IN - 1) * BH;
    const f16 *h1p = &g_h1[(T_IN - 1) & 1][0];
    const float pjb = projb[0];

    for (int t = 0; t < T_OUT; ++t) {
        // phase A: dec0(t); side tasks: emit out[:,t-1], reseed next slot
        if (bid == 0 && tid < Bsz && t >= 1)
            out[(size_t)tid * T_OUT + (t - 1)] = g_pacc[t & 1][tid];
        if (bid == 1 && tid < Bsz)
            g_pacc[(t + 1) & 1][tid] = pjb;

        segs[0] = { h0p, gB_d0, Hd };
        ZERO_ACC(accA);
        pipe_gemm(dsm32, segs, 1, 8, accA, accA, bm, colb, tid, asw, bsw);
        epilogue_lstm(accA, c0, g_bd0, &g_pacc[t & 1][0], g_Wv,
                      &g_d0[t & 1][0], nullptr, nullptr, bm, G16, wm, lane);
        grid_sync();

        // phase B: dec1(t) + fused projection into pacc[(t+1)&1]
        segs[0] = { &g_d0[t & 1][0], gB_x1d, Hd };
        segs[1] = { h1p, gB_d1, Hd };
        ZERO_ACC(accA);
        pipe_gemm(dsm32, segs, 2, 16, accA, accA, bm, colb, tid, asw, bsw);
        epilogue_lstm(accA, c1, g_bd1, nullptr, nullptr,
                      &g_d1[t & 1][0], projW, &g_pacc[(t + 1) & 1][0],
                      bm, G16, wm, lane);
        grid_sync();

        h0p = &g_d0[t & 1][0];
        h1p = &g_d1[t & 1][0];
    }

    // final output column (t = 63): slot (63+1)&1 = 0
    if (bid == 0 && tid < Bsz)
        out[(size_t)tid * T_OUT + (T_OUT - 1)] = g_pacc[0][tid];
}

// ------------------------------- host side ---------------------------------
extern "C" void kernel_launch(void* const* d_in, const int* in_sizes, int n_in,
                              void* d_out, int out_size) {
    const float* x      = (const float*)d_in[0];
    const float* e0Wih  = (const float*)d_in[2];
    const float* e0Whh  = (const float*)d_in[3];
    const float* e0bih  = (const float*)d_in[4];
    const float* e0bhh  = (const float*)d_in[5];
    const float* e1Wih  = (const float*)d_in[6];
    const float* e1Whh  = (const float*)d_in[7];
    const float* e1bih  = (const float*)d_in[8];
    const float* e1bhh  = (const float*)d_in[9];
    const float* d0Wih  = (const float*)d_in[10];
    const float* d0Whh  = (const float*)d_in[11];
    const float* d0bih  = (const float*)d_in[12];
    const float* d0bhh  = (const float*)d_in[13];
    const float* d1Wih  = (const float*)d_in[14];
    const float* d1Whh  = (const float*)d_in[15];
    const float* d1bih  = (const float*)d_in[16];
    const float* d1bhh  = (const float*)d_in[17];
    const float* projW  = (const float*)d_in[18];
    const float* projb  = (const float*)d_in[19];
    float* out = (float*)d_out;

    const long long total = 6LL * N4 * Hd + (long long)N4 * Fin
                          + (long long)Bsz * T_IN * Fin + N4 + Bsz + 1;
    const int nblk = (int)((total + 255) / 256);
    prep_kernel<<<nblk, 256>>>(x,
        e0Wih, e0Whh, e0bih, e0bhh,
        e1Wih, e1Whh, e1bih, e1bhh,
        d0Wih, d0Whh, d0bih, d0bhh,
        d1Wih, d1Whh, d1bih, d1bhh, projb);

    cudaFuncSetAttribute(main_kernel, cudaFuncAttributeMaxDynamicSharedMemorySize, DSMEM);
    main_kernel<<<NBLK, THR, DSMEM>>>(projW, projb, out);
}